// round 6
// baseline (speedup 1.0000x reference)
#include <cuda_runtime.h>
#include <cstdint>
#include <cstddef>

#define N_NODES 100000
#define N_EDGES 1280000
#define D 64

// Per-node pre-GEMM accumulators: [node][128 floats] = fwd(64) | rev(64),
// stored as float4 for 16B-aligned vector reductions. 51.2 MB, fits L2.
__device__ float4 g_S[(size_t)N_NODES * 32];

// ---------------------------------------------------------------------------
// K0: zero the scratch accumulator
// ---------------------------------------------------------------------------
__global__ void k_zero() {
    int i = blockIdx.x * blockDim.x + threadIdx.x;
    if (i < N_NODES * 32) g_S[i] = make_float4(0.f, 0.f, 0.f, 0.f);
}

// ---------------------------------------------------------------------------
// K1: fused edge kernel.
//   - loads a 64-edge tile of edge_feat into SMEM (single DRAM read of edge_feat)
//   - scatter phase: comp = node_feat[src] * edge_feat * norm, vector-reduced
//     into g_S[dst] (fwd or rev half, selected by is_rev)
//   - GEMM phase: edge_out = edge_feat @ rel_weight  (64x64, fp32, 8x8 reg tile)
// 64 threads/block, 20000 blocks (E divisible by 64).
// ---------------------------------------------------------------------------
__global__ __launch_bounds__(64) void k_edge(
    const float* __restrict__ node_feat,
    const float* __restrict__ edge_feat,
    const float* __restrict__ edge_norm,
    const int*   __restrict__ src,
    const int*   __restrict__ dst,
    const int*   __restrict__ is_rev,     // bool marshalled as int32
    const float* __restrict__ rel_w,
    float* __restrict__ edge_out,
    int write_edge)
{
    __shared__ float Xs[64][68];   // [row][k], pad 68 to de-conflict banks
    __shared__ float Wt[64][68];   // [col][k]  (transposed rel_weight)

    const int t  = threadIdx.x;
    const int e0 = blockIdx.x * 64;

    // --- load rel_weight transposed: Wt[c][k] = W[k][c] ---
    #pragma unroll 8
    for (int k = 0; k < 64; k++)
        Wt[t][k] = rel_w[k * 64 + t];

    // --- load edge_feat tile (coalesced, 512B per warp-instruction) ---
    const float4* Xg = reinterpret_cast<const float4*>(edge_feat) + (size_t)e0 * 16;
    #pragma unroll
    for (int it = 0; it < 16; it++) {
        int idx = it * 64 + t;          // 0..1023
        int r  = idx >> 4;
        int kq = idx & 15;
        float4 v = Xg[(size_t)r * 16 + kq];
        *reinterpret_cast<float4*>(&Xs[r][kq * 4]) = v;
    }
    __syncthreads();

    // --- scatter phase: thread t owns edge e0+t ---
    {
        int e = e0 + t;
        int s  = src[e];
        int d  = dst[e];
        float nrm = edge_norm[e];
        int rv = (is_rev[e] != 0) ? 1 : 0;
        const float4* nf = reinterpret_cast<const float4*>(node_feat) + (size_t)s * 16;
        float4* Sp = g_S + (size_t)d * 32 + rv * 16;
        #pragma unroll
        for (int q = 0; q < 16; q++) {
            float4 a = nf[q];
            float4 b = *reinterpret_cast<const float4*>(&Xs[t][q * 4]);
            float vx = a.x * b.x * nrm;
            float vy = a.y * b.y * nrm;
            float vz = a.z * b.z * nrm;
            float vw = a.w * b.w * nrm;
            asm volatile(
                "red.global.add.v4.f32 [%0], {%1, %2, %3, %4};"
                :: "l"(Sp + q), "f"(vx), "f"(vy), "f"(vz), "f"(vw)
                : "memory");
        }
    }

    // --- GEMM phase: edge_out tile = Xs @ W ---
    if (write_edge) {
        const int tx = t & 7;          // col group
        const int ty = t >> 3;         // row group
        float acc[8][8];
        #pragma unroll
        for (int i = 0; i < 8; i++)
            #pragma unroll
            for (int j = 0; j < 8; j++) acc[i][j] = 0.f;

        #pragma unroll 4
        for (int k4 = 0; k4 < 16; k4++) {
            float4 xv[8], wv[8];
            #pragma unroll
            for (int i = 0; i < 8; i++)
                xv[i] = *reinterpret_cast<const float4*>(&Xs[ty + 8 * i][k4 * 4]);
            #pragma unroll
            for (int j = 0; j < 8; j++)
                wv[j] = *reinterpret_cast<const float4*>(&Wt[tx + 8 * j][k4 * 4]);
            #pragma unroll
            for (int i = 0; i < 8; i++)
                #pragma unroll
                for (int j = 0; j < 8; j++) {
                    acc[i][j] += xv[i].x * wv[j].x;
                    acc[i][j] += xv[i].y * wv[j].y;
                    acc[i][j] += xv[i].z * wv[j].z;
                    acc[i][j] += xv[i].w * wv[j].w;
                }
        }

        #pragma unroll
        for (int i = 0; i < 8; i++) {
            float* o = edge_out + (size_t)(e0 + ty + 8 * i) * 64;
            #pragma unroll
            for (int j = 0; j < 8; j++)
                o[tx + 8 * j] = acc[i][j];
        }
    }
}

// ---------------------------------------------------------------------------
// K2: node kernel.
//   node_out = (S_fwd @ in_W + S_rev @ out_W + node_feat @ (diag(loop_rel) loop_W))
//              * 0.3333333 + bias
// Implemented as a 3-chunk K=192 GEMM over 64-node row tiles.
// ---------------------------------------------------------------------------
__global__ __launch_bounds__(64) void k_node(
    const float* __restrict__ node_feat,
    const float* __restrict__ in_w,
    const float* __restrict__ out_w,
    const float* __restrict__ loop_w,
    const float* __restrict__ loop_rel,
    const float* __restrict__ bias,
    float* __restrict__ node_out)
{
    __shared__ float Xs[64][68];
    __shared__ float Wt[64][68];

    const int t  = threadIdx.x;
    const int r0 = blockIdx.x * 64;
    const int tx = t & 7;
    const int ty = t >> 3;
    const float* S = reinterpret_cast<const float*>(g_S);

    float acc[8][8];
    #pragma unroll
    for (int i = 0; i < 8; i++)
        #pragma unroll
        for (int j = 0; j < 8; j++) acc[i][j] = 0.f;

    #pragma unroll 1
    for (int ch = 0; ch < 3; ch++) {
        // weight chunk (transposed); chunk 2 folds loop_rel into loop_w
        if (ch == 2) {
            #pragma unroll 8
            for (int k = 0; k < 64; k++)
                Wt[t][k] = loop_w[k * 64 + t] * loop_rel[k];
        } else {
            const float* W = (ch == 0) ? in_w : out_w;
            #pragma unroll 8
            for (int k = 0; k < 64; k++)
                Wt[t][k] = W[k * 64 + t];
        }

        // X chunk
        const float* Xbase;
        size_t pitch, off;
        if (ch == 0)      { Xbase = S;         pitch = 128; off = 0;  }
        else if (ch == 1) { Xbase = S;         pitch = 128; off = 64; }
        else              { Xbase = node_feat; pitch = 64;  off = 0;  }

        #pragma unroll
        for (int it = 0; it < 16; it++) {
            int idx = it * 64 + t;
            int r  = idx >> 4;
            int kq = idx & 15;
            int gr = r0 + r;
            float4 v = make_float4(0.f, 0.f, 0.f, 0.f);
            if (gr < N_NODES)
                v = *reinterpret_cast<const float4*>(Xbase + (size_t)gr * pitch + off + kq * 4);
            *reinterpret_cast<float4*>(&Xs[r][kq * 4]) = v;
        }
        __syncthreads();

        #pragma unroll 4
        for (int k4 = 0; k4 < 16; k4++) {
            float4 xv[8], wv[8];
            #pragma unroll
            for (int i = 0; i < 8; i++)
                xv[i] = *reinterpret_cast<const float4*>(&Xs[ty + 8 * i][k4 * 4]);
            #pragma unroll
            for (int j = 0; j < 8; j++)
                wv[j] = *reinterpret_cast<const float4*>(&Wt[tx + 8 * j][k4 * 4]);
            #pragma unroll
            for (int i = 0; i < 8; i++)
                #pragma unroll
                for (int j = 0; j < 8; j++) {
                    acc[i][j] += xv[i].x * wv[j].x;
                    acc[i][j] += xv[i].y * wv[j].y;
                    acc[i][j] += xv[i].z * wv[j].z;
                    acc[i][j] += xv[i].w * wv[j].w;
                }
        }
        __syncthreads();
    }

    #pragma unroll
    for (int i = 0; i < 8; i++) {
        int r = r0 + ty + 8 * i;
        if (r < N_NODES) {
            float* o = node_out + (size_t)r * 64;
            #pragma unroll
            for (int j = 0; j < 8; j++) {
                int c = tx + 8 * j;
                o[c] = acc[i][j] * 0.3333333f + __ldg(&bias[c]);
            }
        }
    }
}

// ---------------------------------------------------------------------------
// kernel_launch
// Inputs (metadata order == setup_inputs dict order):
//   0 node_feat [N,64] f32      1 edge_feat [E,64] f32   2 edge_norm [E,1] f32
//   3 src [E] i32               4 dst [E] i32            5 is_rev [E] int32 (bool)
//   6 in_weight [64,64]         7 out_weight [64,64]     8 rel_weight [64,64]
//   9 loop_weight [64,64]      10 loop_rel [1,64]       11 bias [64]
// Output: node_out [N,64] followed by edge_out [E,64], f32.
// ---------------------------------------------------------------------------
extern "C" void kernel_launch(void* const* d_in, const int* in_sizes, int n_in,
                              void* d_out, int out_size)
{
    const float* node_feat = (const float*)d_in[0];
    const float* edge_feat = (const float*)d_in[1];
    const float* edge_norm = (const float*)d_in[2];
    const int*   src       = (const int*)d_in[3];
    const int*   dst       = (const int*)d_in[4];
    const int*   is_rev    = (const int*)d_in[5];
    const float* in_w      = (const float*)d_in[6];
    const float* out_w     = (const float*)d_in[7];
    const float* rel_w     = (const float*)d_in[8];
    const float* loop_w    = (const float*)d_in[9];
    const float* loop_rel  = (const float*)d_in[10];
    const float* bias      = (const float*)d_in[11];

    float* out      = (float*)d_out;
    float* node_out = out;

    // Defensive: only write edge_out if the output buffer actually has room
    // for both tensors (expected out_size = (N+E)*64).
    int write_edge = (out_size >= (N_NODES + N_EDGES) * D) ? 1 : 0;
    float* edge_out = write_edge ? (out + (size_t)N_NODES * D) : nullptr;

    // K0: zero scratch
    {
        int n = N_NODES * 32;
        k_zero<<<(n + 255) / 256, 256>>>();
    }

    // K1: fused edge scatter + edge_out GEMM
    k_edge<<<N_EDGES / 64, 64>>>(node_feat, edge_feat, edge_norm,
                                 src, dst, is_rev, rel_w, edge_out, write_edge);

    // K2: node GEMM + epilogue
    k_node<<<(N_NODES + 63) / 64, 64>>>(node_feat, in_w, out_w,
                                        loop_w, loop_rel, bias, node_out);
}

// round 8
// speedup vs baseline: 1.1035x; 1.1035x over previous
#include <cuda_runtime.h>
#include <cstdint>
#include <cstddef>

#define N_NODES 100000
#define N_EDGES 1280000
#define D 64

typedef unsigned long long u64;

// Packed fp32x2 FMA (Blackwell sm_100a+). One instruction = 2 independent FMAs.
// Packs are formed over adjacent K indices, so both operands come straight out
// of LDS.128 register pairs — no packing MOVs. Partial sums (even-k, odd-k)
// are folded with one FADD at the end.
#define FMA2(acc, a, b) \
    asm("fma.rn.f32x2 %0, %1, %2, %0;" : "+l"(acc) : "l"(a), "l"(b))

union F2U { u64 u; float2 f; };

// Per-node pre-GEMM accumulators: [node][128 floats] = fwd(64) | rev(64),
// stored as float4 for 16B-aligned vector reductions. 51.2 MB, fits L2.
__device__ float4 g_S[(size_t)N_NODES * 32];

// ---------------------------------------------------------------------------
// K0: zero the scratch accumulator
// ---------------------------------------------------------------------------
__global__ void k_zero() {
    int i = blockIdx.x * blockDim.x + threadIdx.x;
    if (i < N_NODES * 32) g_S[i] = make_float4(0.f, 0.f, 0.f, 0.f);
}

// ---------------------------------------------------------------------------
// K1: fused edge kernel.
//   - loads a 64-edge tile of edge_feat into SMEM (single DRAM read)
//   - scatter phase: comp = node_feat[src] * edge_feat * norm, vector-reduced
//     into g_S[dst] (fwd or rev half, selected by is_rev)
//   - GEMM phase: edge_out = edge_feat @ rel_weight (64x64, fp32x2, 8x8 tile)
// ---------------------------------------------------------------------------
__global__ __launch_bounds__(64) void k_edge(
    const float* __restrict__ node_feat,
    const float* __restrict__ edge_feat,
    const float* __restrict__ edge_norm,
    const int*   __restrict__ src,
    const int*   __restrict__ dst,
    const int*   __restrict__ is_rev,     // bool marshalled as int32
    const float* __restrict__ rel_w,
    float* __restrict__ edge_out,
    int write_edge)
{
    __shared__ float Xs[64][68];   // [row][k], pad 68: row stride 272B (16B-aligned)
    __shared__ float Wt[64][68];   // [col][k]  (transposed rel_weight)

    const int t  = threadIdx.x;
    const int e0 = blockIdx.x * 64;

    // --- load rel_weight transposed: Wt[c][k] = W[k][c] ---
    #pragma unroll 8
    for (int k = 0; k < 64; k++)
        Wt[t][k] = rel_w[k * 64 + t];

    // --- load edge_feat tile (coalesced) ---
    const float4* Xg = reinterpret_cast<const float4*>(edge_feat) + (size_t)e0 * 16;
    #pragma unroll
    for (int it = 0; it < 16; it++) {
        int idx = it * 64 + t;          // 0..1023
        int r  = idx >> 4;
        int kq = idx & 15;
        float4 v = Xg[(size_t)r * 16 + kq];
        *reinterpret_cast<float4*>(&Xs[r][kq * 4]) = v;
    }
    __syncthreads();

    // --- scatter phase: thread t owns edge e0+t ---
    {
        int e = e0 + t;
        int s  = src[e];
        int d  = dst[e];
        float nrm = edge_norm[e];
        int rv = (is_rev[e] != 0) ? 1 : 0;
        const float4* nf = reinterpret_cast<const float4*>(node_feat) + (size_t)s * 16;
        float4* Sp = g_S + (size_t)d * 32 + rv * 16;
        #pragma unroll
        for (int q = 0; q < 16; q++) {
            float4 a = nf[q];
            float4 b = *reinterpret_cast<const float4*>(&Xs[t][q * 4]);
            float vx = a.x * b.x * nrm;
            float vy = a.y * b.y * nrm;
            float vz = a.z * b.z * nrm;
            float vw = a.w * b.w * nrm;
            asm volatile(
                "red.global.add.v4.f32 [%0], {%1, %2, %3, %4};"
                :: "l"(Sp + q), "f"(vx), "f"(vy), "f"(vz), "f"(vw)
                : "memory");
        }
    }

    // --- GEMM phase: edge_out tile = Xs @ W, packed fp32x2 over K pairs ---
    if (write_edge) {
        const int tx = t & 7;          // col group (col = tx + 8j)
        const int ty = t >> 3;         // row group (row = ty + 8i)
        u64 acc[8][8];
        #pragma unroll
        for (int i = 0; i < 8; i++)
            #pragma unroll
            for (int j = 0; j < 8; j++) acc[i][j] = 0ull;   // {0.f, 0.f}

        #pragma unroll 4
        for (int k4 = 0; k4 < 16; k4++) {
            ulonglong2 xv[8], wv[8];   // each = 4 k's = 2 packed pairs
            #pragma unroll
            for (int i = 0; i < 8; i++)
                xv[i] = *reinterpret_cast<const ulonglong2*>(&Xs[ty + 8 * i][k4 * 4]);
            #pragma unroll
            for (int j = 0; j < 8; j++)
                wv[j] = *reinterpret_cast<const ulonglong2*>(&Wt[tx + 8 * j][k4 * 4]);
            #pragma unroll
            for (int i = 0; i < 8; i++)
                #pragma unroll
                for (int j = 0; j < 8; j++)
                    FMA2(acc[i][j], xv[i].x, wv[j].x);
            #pragma unroll
            for (int i = 0; i < 8; i++)
                #pragma unroll
                for (int j = 0; j < 8; j++)
                    FMA2(acc[i][j], xv[i].y, wv[j].y);
        }

        #pragma unroll
        for (int i = 0; i < 8; i++) {
            float* o = edge_out + (size_t)(e0 + ty + 8 * i) * 64;
            #pragma unroll
            for (int j = 0; j < 8; j++) {
                F2U c; c.u = acc[i][j];
                o[tx + 8 * j] = c.f.x + c.f.y;
            }
        }
    }
}

// ---------------------------------------------------------------------------
// K2: node kernel.
//   node_out = (S_fwd @ in_W + S_rev @ out_W + node_feat @ (diag(loop_rel) loop_W))
//              * 0.3333333 + bias
// 3-chunk K=192 GEMM over 64-node row tiles, packed fp32x2.
// ---------------------------------------------------------------------------
__global__ __launch_bounds__(64) void k_node(
    const float* __restrict__ node_feat,
    const float* __restrict__ in_w,
    const float* __restrict__ out_w,
    const float* __restrict__ loop_w,
    const float* __restrict__ loop_rel,
    const float* __restrict__ bias,
    float* __restrict__ node_out)
{
    __shared__ float Xs[64][68];
    __shared__ float Wt[64][68];

    const int t  = threadIdx.x;
    const int r0 = blockIdx.x * 64;
    const int tx = t & 7;
    const int ty = t >> 3;
    const float* S = reinterpret_cast<const float*>(g_S);

    u64 acc[8][8];
    #pragma unroll
    for (int i = 0; i < 8; i++)
        #pragma unroll
        for (int j = 0; j < 8; j++) acc[i][j] = 0ull;

    #pragma unroll 1
    for (int ch = 0; ch < 3; ch++) {
        // weight chunk (transposed); chunk 2 folds loop_rel into loop_w
        if (ch == 2) {
            #pragma unroll 8
            for (int k = 0; k < 64; k++)
                Wt[t][k] = loop_w[k * 64 + t] * loop_rel[k];
        } else {
            const float* W = (ch == 0) ? in_w : out_w;
            #pragma unroll 8
            for (int k = 0; k < 64; k++)
                Wt[t][k] = W[k * 64 + t];
        }

        // X chunk
        const float* Xbase;
        size_t pitch, off;
        if (ch == 0)      { Xbase = S;         pitch = 128; off = 0;  }
        else if (ch == 1) { Xbase = S;         pitch = 128; off = 64; }
        else              { Xbase = node_feat; pitch = 64;  off = 0;  }

        #pragma unroll
        for (int it = 0; it < 16; it++) {
            int idx = it * 64 + t;
            int r  = idx >> 4;
            int kq = idx & 15;
            int gr = r0 + r;
            float4 v = make_float4(0.f, 0.f, 0.f, 0.f);
            if (gr < N_NODES)
                v = *reinterpret_cast<const float4*>(Xbase + (size_t)gr * pitch + off + kq * 4);
            *reinterpret_cast<float4*>(&Xs[r][kq * 4]) = v;
        }
        __syncthreads();

        #pragma unroll 4
        for (int k4 = 0; k4 < 16; k4++) {
            ulonglong2 xv[8], wv[8];
            #pragma unroll
            for (int i = 0; i < 8; i++)
                xv[i] = *reinterpret_cast<const ulonglong2*>(&Xs[ty + 8 * i][k4 * 4]);
            #pragma unroll
            for (int j = 0; j < 8; j++)
                wv[j] = *reinterpret_cast<const ulonglong2*>(&Wt[tx + 8 * j][k4 * 4]);
            #pragma unroll
            for (int i = 0; i < 8; i++)
                #pragma unroll
                for (int j = 0; j < 8; j++)
                    FMA2(acc[i][j], xv[i].x, wv[j].x);
            #pragma unroll
            for (int i = 0; i < 8; i++)
                #pragma unroll
                for (int j = 0; j < 8; j++)
                    FMA2(acc[i][j], xv[i].y, wv[j].y);
        }
        __syncthreads();
    }

    #pragma unroll
    for (int i = 0; i < 8; i++) {
        int r = r0 + ty + 8 * i;
        if (r < N_NODES) {
            float* o = node_out + (size_t)r * 64;
            #pragma unroll
            for (int j = 0; j < 8; j++) {
                int c = tx + 8 * j;
                F2U cv; cv.u = acc[i][j];
                o[c] = (cv.f.x + cv.f.y) * 0.3333333f + __ldg(&bias[c]);
            }
        }
    }
}

// ---------------------------------------------------------------------------
// kernel_launch
// Inputs (metadata order == setup_inputs dict order):
//   0 node_feat [N,64] f32      1 edge_feat [E,64] f32   2 edge_norm [E,1] f32
//   3 src [E] i32               4 dst [E] i32            5 is_rev [E] int32 (bool)
//   6 in_weight [64,64]         7 out_weight [64,64]     8 rel_weight [64,64]
//   9 loop_weight [64,64]      10 loop_rel [1,64]       11 bias [64]
// Output: node_out [N,64] followed by edge_out [E,64], f32.
// ---------------------------------------------------------------------------
extern "C" void kernel_launch(void* const* d_in, const int* in_sizes, int n_in,
                              void* d_out, int out_size)
{
    const float* node_feat = (const float*)d_in[0];
    const float* edge_feat = (const float*)d_in[1];
    const float* edge_norm = (const float*)d_in[2];
    const int*   src       = (const int*)d_in[3];
    const int*   dst       = (const int*)d_in[4];
    const int*   is_rev    = (const int*)d_in[5];
    const float* in_w      = (const float*)d_in[6];
    const float* out_w     = (const float*)d_in[7];
    const float* rel_w     = (const float*)d_in[8];
    const float* loop_w    = (const float*)d_in[9];
    const float* loop_rel  = (const float*)d_in[10];
    const float* bias      = (const float*)d_in[11];

    float* out      = (float*)d_out;
    float* node_out = out;

    int write_edge = (out_size >= (N_NODES + N_EDGES) * D) ? 1 : 0;
    float* edge_out = write_edge ? (out + (size_t)N_NODES * D) : nullptr;

    // K0: zero scratch
    {
        int n = N_NODES * 32;
        k_zero<<<(n + 255) / 256, 256>>>();
    }

    // K1: fused edge scatter + edge_out GEMM
    k_edge<<<N_EDGES / 64, 64>>>(node_feat, edge_feat, edge_norm,
                                 src, dst, is_rev, rel_w, edge_out, write_edge);

    // K2: node GEMM + epilogue
    k_node<<<(N_NODES + 63) / 64, 64>>>(node_feat, in_w, out_w,
                                        loop_w, loop_rel, bias, node_out);
}